// round 15
// baseline (speedup 1.0000x reference)
#include <cuda_runtime.h>
#include <cuda_fp16.h>
#include <cstdint>

#define NUM_E 4
#define DIM_H 2048
#define DIM_I 2048
#define TOK   4096
#define GRP   512

__device__ __half g_A1   [(size_t)NUM_E * TOK * DIM_H];
__device__ __half g_W1t  [(size_t)NUM_E * (2*DIM_I) * DIM_H];
__device__ __half g_W2t  [(size_t)NUM_E * DIM_H * DIM_I];
__device__ __half g_inter[(size_t)NUM_E * TOK * DIM_I];

__device__ __forceinline__ uint32_t smem_u32(const void* p){
    uint32_t a;
    asm("{ .reg .u64 t; cvta.to.shared.u64 t, %1; cvt.u32.u64 %0, t; }" : "=r"(a) : "l"(p));
    return a;
}
__device__ __forceinline__ void cp16(uint32_t s, const void* g){
    asm volatile("cp.async.cg.shared.global [%0], [%1], 16;" :: "r"(s), "l"(g) : "memory");
}
__device__ __forceinline__ void mma_f16(float* c, const uint32_t* a, const uint32_t* b){
    asm volatile(
        "mma.sync.aligned.m16n8k16.row.col.f32.f16.f16.f32 "
        "{%0,%1,%2,%3}, {%4,%5,%6,%7}, {%8,%9}, {%0,%1,%2,%3};"
        : "+f"(c[0]), "+f"(c[1]), "+f"(c[2]), "+f"(c[3])
        : "r"(a[0]), "r"(a[1]), "r"(a[2]), "r"(a[3]), "r"(b[0]), "r"(b[1]));
}
__device__ __forceinline__ void ldsm4(uint32_t* r, uint32_t addr){
    asm volatile("ldmatrix.sync.aligned.m8n8.x4.shared.b16 {%0,%1,%2,%3}, [%4];"
        : "=r"(r[0]), "=r"(r[1]), "=r"(r[2]), "=r"(r[3]) : "r"(addr));
}

#define MBARRIER_INIT(addr, count) \
    asm volatile("mbarrier.init.shared.b64 [%0], %1;" :: "r"((uint32_t)(addr)), "r"((uint32_t)(count)) : "memory")

#define MBARRIER_ARRIVE(addr) \
    asm volatile("mbarrier.arrive.shared.b64 _, [%0];" :: "r"((uint32_t)(addr)) : "memory")

#define MBARRIER_WAIT_PARITY(mbar, par) do { \
    uint32_t _m = (uint32_t)(mbar), _p = (uint32_t)(par), _d; \
    asm volatile("{\n\t.reg .pred p;\n\t" \
        "mbarrier.try_wait.parity.acquire.cta.shared::cta.b64 p, [%1], %2;\n\t" \
        "selp.b32 %0, 1, 0, p;\n\t}" : "=r"(_d) : "r"(_m), "r"(_p) : "memory"); \
    if (!_d) { \
        asm volatile("{\n\t.reg .pred P1;\n\t" \
            "WL_%=:\n\t" \
            "mbarrier.try_wait.parity.acquire.cta.shared::cta.b64 P1, [%0], %1, 0x989680;\n\t" \
            "@P1 bra.uni WD_%=;\n\t" \
            "bra.uni WL_%=;\n\t" \
            "WD_%=:\n\t}" :: "r"(_m), "r"(_p) : "memory"); \
    } \
} while(0)

// ---------------- fused prep kernel ----------------
// blocks [0, 32768)           : W1 transpose (+permuted rows)
// blocks [32768, 49152)       : W2 transpose (+delta16 cols, phi32 rows)
// blocks [49152, 51200)       : x gather -> fp16
#define PREP_W1_BLKS 32768
#define PREP_W2_BLKS 16384
#define PREP_GX_BLKS 2048
#define PREP_BLKS    (PREP_W1_BLKS + PREP_W2_BLKS + PREP_GX_BLKS)

__device__ __forceinline__ int permW1(int d){
    return (d < DIM_I) ? ((d >> 7) * 256 + ((d & 127) << 1))
                       : (((d - DIM_I) >> 7) * 256 + (((d - DIM_I) & 127) << 1) + 1);
}

__global__ void k_prep(const float* __restrict__ x,
                       const float* __restrict__ w1,
                       const float* __restrict__ w2){
    __shared__ float tile[32][33];
    int bid = blockIdx.x;
    int tid = threadIdx.x;
    int tx = tid & 31, ty = tid >> 5;

    if (bid < PREP_W1_BLKS){
        int e  = bid >> 13;
        int d0 = (bid & 127) * 32;
        int h0 = ((bid >> 7) & 63) * 32;
        const float* src = w1 + (size_t)e * DIM_H * (2*DIM_I);
        #pragma unroll
        for (int i = 0; i < 4; i++)
            tile[ty + 8*i][tx] = src[(size_t)(h0 + ty + 8*i) * (2*DIM_I) + d0 + tx];
        __syncthreads();
        __half* dst = g_W1t + (size_t)e * (2*DIM_I) * DIM_H;
        #pragma unroll
        for (int i = 0; i < 4; i++){
            int r = permW1(d0 + ty + 8*i);
            dst[(size_t)r * DIM_H + h0 + tx] = __float2half_rn(tile[tx][ty + 8*i]);
        }
    } else if (bid < PREP_W1_BLKS + PREP_W2_BLKS){
        int b2 = bid - PREP_W1_BLKS;
        int e  = b2 >> 12;
        int h0 = (b2 & 63) * 32;
        int i0 = ((b2 >> 6) & 63) * 32;
        const float* src = w2 + (size_t)e * DIM_I * DIM_H;
        #pragma unroll
        for (int i = 0; i < 4; i++)
            tile[ty + 8*i][tx] = src[(size_t)(i0 + ty + 8*i) * DIM_H + h0 + tx];
        __syncthreads();
        __half* dst = g_W2t + (size_t)e * DIM_H * DIM_I;
        int iL = i0 + tx;
        int ipos = (iL & ~15) | (((iL & 3) << 2) | ((iL >> 2) & 3));
        #pragma unroll
        for (int i = 0; i < 4; i++){
            int h = h0 + ty + 8*i;
            int hl = h & 31;
            int hpos = (h & ~31) | ((((hl >> 1) & 3) << 3) | (((hl >> 3) & 3) << 1) | (hl & 1));
            dst[(size_t)hpos * DIM_I + ipos] = __float2half_rn(tile[tx][ty + 8*i]);
        }
    } else {
        int b3 = bid - PREP_W1_BLKS - PREP_W2_BLKS;
        size_t n4 = (size_t)NUM_E * TOK * DIM_H / 4;
        for (size_t o4 = (size_t)b3 * 256 + tid; o4 < n4;
             o4 += (size_t)PREP_GX_BLKS * 256){
            uint32_t h4 = (uint32_t)(o4 & 511u);
            uint32_t th = (uint32_t)(o4 >> 9);
            uint32_t t  = th & (TOK - 1);
            uint32_t e  = th >> 12;
            uint32_t b  = t >> 9, g = t & (GRP - 1);
            size_t src4 = ((size_t)(b*2048u + g*4u + e) << 9) + h4;
            float4 v = reinterpret_cast<const float4*>(x)[src4];
            __half2 h01 = __floats2half2_rn(v.x, v.y);
            __half2 h23 = __floats2half2_rn(v.z, v.w);
            uint2 pk;
            pk.x = *reinterpret_cast<uint32_t*>(&h01);
            pk.y = *reinterpret_cast<uint32_t*>(&h23);
            reinterpret_cast<uint2*>(g_A1)[o4] = pk;
        }
    }
}

// ---------------- pipelined fp16 mma.sync GEMM (mbarrier pipeline) ----------------
// CTA 128x128, 8 warps (2x4) of 64x32, KC=64 halves (128B rows), 3 stages, 2 CTA/SM.
// Empty barrier: per-warp arrive (count 8, lane 0 only).
#define STAGE_B   32768
#define A_BYTES   16384
#define GEMM_SMEM (3 * STAGE_B + 64)

template<int FUSE>
__global__ void __launch_bounds__(256, 2) k_gemm(float* __restrict__ out_){
    constexpr int K = 2048, KIT = 32;   // KC = 64 halves per iter
    constexpr int NTOT = (FUSE == 0) ? 4096 : 2048;

    const __half* Ag = (FUSE == 0) ? g_A1  : g_inter;
    const __half* Bg = (FUSE == 0) ? g_W1t : g_W2t;

    extern __shared__ char smem[];
    const uint32_t sb = smem_u32(smem);
    const uint32_t full_b  = sb + 3 * STAGE_B;
    const uint32_t empty_b = full_b + 24;

    const int tid = threadIdx.x;
    const int wid = tid >> 5, ln = tid & 31;
    const int wm = wid & 1, wn = wid >> 1;      // 2 x 4 warp grid
    const int gid = ln >> 2, tig = ln & 3;

    const int e = blockIdx.z, mt_cta = blockIdx.y, nt_cta = blockIdx.x;
    const __half* Ae = Ag + (size_t)e * TOK  * K + (size_t)mt_cta * 128 * K;
    const __half* Be = Bg + (size_t)e * NTOT * K + (size_t)nt_cta * 128 * K;

    const uint32_t xk   = (uint32_t)(ln & 7);
    const uint32_t axor = ((uint32_t)(ln >> 4) & 1u) ^ xk;
    const uint32_t bxor = ((uint32_t)(ln >> 3) & 1u) ^ xk;
    const uint32_t aRow = (uint32_t)(wm * 64 + (ln & 15));
    const uint32_t bRow = (uint32_t)(wn * 32 + ((ln >> 4) & 1) * 8 + (ln & 7));

    if (tid == 0){
        #pragma unroll
        for (int s = 0; s < 3; s++){
            MBARRIER_INIT(full_b  + 8*s, 256);
            MBARRIER_INIT(empty_b + 8*s, 8);
        }
    }
    __syncthreads();

    auto load_stage = [&](int kc, int s){
        uint32_t stA = sb + (uint32_t)s * STAGE_B;
        uint32_t stB = stA + A_BYTES;
        const __half* gA = Ae + kc * 64;
        const __half* gB = Be + kc * 64;
        #pragma unroll
        for (int i = 0; i < 4; i++){
            int c = tid + i * 256; int row = c >> 3, ch = c & 7;
            cp16(stA + (uint32_t)row * 128u + (uint32_t)((ch ^ (row & 7)) << 4),
                 gA + (size_t)row * K + ch * 8);
        }
        #pragma unroll
        for (int i = 0; i < 4; i++){
            int c = tid + i * 256; int row = c >> 3, ch = c & 7;
            cp16(stB + (uint32_t)row * 128u + (uint32_t)((ch ^ (row & 7)) << 4),
                 gB + (size_t)row * K + ch * 8);
        }
        asm volatile("cp.async.mbarrier.arrive.noinc.shared.b64 [%0];"
                     :: "r"(full_b + 8*s) : "memory");
    };

    float acc[4][4][4];
    #pragma unroll
    for (int mt = 0; mt < 4; mt++)
        #pragma unroll
        for (int nt = 0; nt < 4; nt++)
            #pragma unroll
            for (int q = 0; q < 4; q++) acc[mt][nt][q] = 0.f;

    load_stage(0, 0);
    load_stage(1, 1);

    int sc = 0, pc = 0;
    int sl = 2, jp = 0;

    for (int k = 0; k < KIT; k++){
        MBARRIER_WAIT_PARITY(full_b + 8*sc, pc);

        uint32_t stA = sb + (uint32_t)sc * STAGE_B;
        uint32_t aBase = stA + aRow * 128u;
        uint32_t bBase = stA + A_BYTES + bRow * 128u;
        #pragma unroll
        for (int kk = 0; kk < 4; kk++){            // 4 x K16
            uint32_t c0 = (uint32_t)(kk << 1);
            uint32_t aoff = ((c0 ^ axor) << 4);
            uint32_t boff = ((c0 ^ bxor) << 4);
            uint32_t af[4][4], bf[4][2];
            #pragma unroll
            for (int mt = 0; mt < 4; mt++)
                ldsm4(af[mt], aBase + (uint32_t)mt * 2048u + aoff);
            #pragma unroll
            for (int j = 0; j < 2; j++){
                uint32_t r4[4];
                ldsm4(r4, bBase + (uint32_t)j * 2048u + boff);
                bf[2*j][0] = r4[0]; bf[2*j][1] = r4[1];
                bf[2*j+1][0] = r4[2]; bf[2*j+1][1] = r4[3];
            }
            #pragma unroll
            for (int mt = 0; mt < 4; mt++)
                #pragma unroll
                for (int nt = 0; nt < 4; nt++)
                    mma_f16(acc[mt][nt], af[mt], bf[nt]);
        }

        if (ln == 0) MBARRIER_ARRIVE(empty_b + 8*sc);
        if (++sc == 3){ sc = 0; pc ^= 1; }

        int kl = k + 2;
        if (kl < KIT){
            if (jp >= 1) MBARRIER_WAIT_PARITY(empty_b + 8*sl, (jp - 1) & 1);
            load_stage(kl, sl);
            if (++sl == 3){ sl = 0; jp++; }
        }
    }

    // ---------------- epilogue ----------------
    if (FUSE == 0){
        __half* ip = g_inter + (size_t)e * TOK * DIM_I;
        int p0 = nt_cta * 64 + wn * 16 + tig * 4;
        #pragma unroll
        for (int mt = 0; mt < 4; mt++){
            int rA = mt_cta * 128 + wm * 64 + mt * 16 + gid;
            __half h0[4], h1[4];
            #pragma unroll
            for (int nt = 0; nt < 4; nt++){
                float g0 = acc[mt][nt][0], u0 = acc[mt][nt][1];
                float g1 = acc[mt][nt][2], u1 = acc[mt][nt][3];
                h0[nt] = __float2half_rn(u0 * (g0 / (1.f + __expf(-g0))));
                h1[nt] = __float2half_rn(u1 * (g1 / (1.f + __expf(-g1))));
            }
            __half2 a0 = __halves2half2(h0[0], h0[1]);
            __half2 a1 = __halves2half2(h0[2], h0[3]);
            __half2 b0 = __halves2half2(h1[0], h1[1]);
            __half2 b1 = __halves2half2(h1[2], h1[3]);
            uint2 u;
            u.x = *reinterpret_cast<uint32_t*>(&a0);
            u.y = *reinterpret_cast<uint32_t*>(&a1);
            *reinterpret_cast<uint2*>(ip + (size_t)rA * DIM_I + p0) = u;
            u.x = *reinterpret_cast<uint32_t*>(&b0);
            u.y = *reinterpret_cast<uint32_t*>(&b1);
            *reinterpret_cast<uint2*>(ip + (size_t)(rA + 8) * DIM_I + p0) = u;
        }
    } else {
        #pragma unroll
        for (int mt = 0; mt < 4; mt++){
            int rA = mt_cta * 128 + wm * 64 + mt * 16 + gid;
            int b0 = rA >> 9, g0 = rA & (GRP - 1);
            int b1 = (rA + 8) >> 9, g1 = (rA + 8) & (GRP - 1);
            size_t o0 = ((size_t)(b0 * 2048 + g0 * 4 + e)) << 11;
            size_t o1 = ((size_t)(b1 * 2048 + g1 * 4 + e)) << 11;
            int hb = nt_cta * 128 + wn * 32 + tig * 8;
            *reinterpret_cast<float4*>(out_ + o0 + hb) =
                make_float4(acc[mt][0][0], acc[mt][0][1], acc[mt][1][0], acc[mt][1][1]);
            *reinterpret_cast<float4*>(out_ + o0 + hb + 4) =
                make_float4(acc[mt][2][0], acc[mt][2][1], acc[mt][3][0], acc[mt][3][1]);
            *reinterpret_cast<float4*>(out_ + o1 + hb) =
                make_float4(acc[mt][0][2], acc[mt][0][3], acc[mt][1][2], acc[mt][1][3]);
            *reinterpret_cast<float4*>(out_ + o1 + hb + 4) =
                make_float4(acc[mt][2][2], acc[mt][2][3], acc[mt][3][2], acc[mt][3][3]);
        }
    }
}

extern "C" void kernel_launch(void* const* d_in, const int* in_sizes, int n_in,
                              void* d_out, int out_size) {
    const float* x  = (const float*)d_in[0];
    const float* w1 = (const float*)d_in[1];
    const float* w2 = (const float*)d_in[2];
    float* out = (float*)d_out;

    cudaFuncSetAttribute(k_gemm<0>, cudaFuncAttributeMaxDynamicSharedMemorySize, GEMM_SMEM);
    cudaFuncSetAttribute(k_gemm<1>, cudaFuncAttributeMaxDynamicSharedMemorySize, GEMM_SMEM);

    k_prep<<<PREP_BLKS, 256>>>(x, w1, w2);
    k_gemm<0><<<dim3(32, 32, 4), 256, GEMM_SMEM>>>(nullptr);
    k_gemm<1><<<dim3(16, 32, 4), 256, GEMM_SMEM>>>(out);
}

// round 16
// speedup vs baseline: 1.0064x; 1.0064x over previous
#include <cuda_runtime.h>
#include <cuda_fp16.h>
#include <cstdint>

#define NUM_E 4
#define DIM_H 2048
#define DIM_I 2048
#define TOK   4096
#define GRP   512

__device__ __half g_A1   [(size_t)NUM_E * TOK * DIM_H];
__device__ __half g_W1t  [(size_t)NUM_E * (2*DIM_I) * DIM_H];
__device__ __half g_W2t  [(size_t)NUM_E * DIM_H * DIM_I];
__device__ __half g_inter[(size_t)NUM_E * TOK * DIM_I];

__device__ __forceinline__ uint32_t smem_u32(const void* p){
    uint32_t a;
    asm("{ .reg .u64 t; cvta.to.shared.u64 t, %1; cvt.u32.u64 %0, t; }" : "=r"(a) : "l"(p));
    return a;
}
__device__ __forceinline__ void cp16(uint32_t s, const void* g){
    asm volatile("cp.async.cg.shared.global [%0], [%1], 16;" :: "r"(s), "l"(g) : "memory");
}
__device__ __forceinline__ void mma_f16(float* c, const uint32_t* a, const uint32_t* b){
    asm volatile(
        "mma.sync.aligned.m16n8k16.row.col.f32.f16.f16.f32 "
        "{%0,%1,%2,%3}, {%4,%5,%6,%7}, {%8,%9}, {%0,%1,%2,%3};"
        : "+f"(c[0]), "+f"(c[1]), "+f"(c[2]), "+f"(c[3])
        : "r"(a[0]), "r"(a[1]), "r"(a[2]), "r"(a[3]), "r"(b[0]), "r"(b[1]));
}
__device__ __forceinline__ void ldsm4(uint32_t* r, uint32_t addr){
    asm volatile("ldmatrix.sync.aligned.m8n8.x4.shared.b16 {%0,%1,%2,%3}, [%4];"
        : "=r"(r[0]), "=r"(r[1]), "=r"(r[2]), "=r"(r[3]) : "r"(addr));
}

#define MBARRIER_INIT(addr, count) \
    asm volatile("mbarrier.init.shared.b64 [%0], %1;" :: "r"((uint32_t)(addr)), "r"((uint32_t)(count)) : "memory")

#define MBARRIER_ARRIVE(addr) \
    asm volatile("mbarrier.arrive.shared.b64 _, [%0];" :: "r"((uint32_t)(addr)) : "memory")

#define MBARRIER_WAIT_PARITY(mbar, par) do { \
    uint32_t _m = (uint32_t)(mbar), _p = (uint32_t)(par), _d; \
    asm volatile("{\n\t.reg .pred p;\n\t" \
        "mbarrier.try_wait.parity.acquire.cta.shared::cta.b64 p, [%1], %2;\n\t" \
        "selp.b32 %0, 1, 0, p;\n\t}" : "=r"(_d) : "r"(_m), "r"(_p) : "memory"); \
    if (!_d) { \
        asm volatile("{\n\t.reg .pred P1;\n\t" \
            "WL_%=:\n\t" \
            "mbarrier.try_wait.parity.acquire.cta.shared::cta.b64 P1, [%0], %1, 0x989680;\n\t" \
            "@P1 bra.uni WD_%=;\n\t" \
            "bra.uni WL_%=;\n\t" \
            "WD_%=:\n\t}" :: "r"(_m), "r"(_p) : "memory"); \
    } \
} while(0)

// ---------------- fused prep kernel ----------------
// blocks [0, 32768)           : W1 transpose (+permuted rows)
// blocks [32768, 49152)       : W2 transpose (+delta16 cols, phi32 rows)
// blocks [49152, 51200)       : x gather -> fp16
#define PREP_W1_BLKS 32768
#define PREP_W2_BLKS 16384
#define PREP_GX_BLKS 2048
#define PREP_BLKS    (PREP_W1_BLKS + PREP_W2_BLKS + PREP_GX_BLKS)

__device__ __forceinline__ int permW1(int d){
    return (d < DIM_I) ? ((d >> 7) * 256 + ((d & 127) << 1))
                       : (((d - DIM_I) >> 7) * 256 + (((d - DIM_I) & 127) << 1) + 1);
}

__global__ void k_prep(const float* __restrict__ x,
                       const float* __restrict__ w1,
                       const float* __restrict__ w2){
    __shared__ float tile[32][33];
    int bid = blockIdx.x;
    int tid = threadIdx.x;
    int tx = tid & 31, ty = tid >> 5;

    if (bid < PREP_W1_BLKS){
        int e  = bid >> 13;
        int d0 = (bid & 127) * 32;
        int h0 = ((bid >> 7) & 63) * 32;
        const float* src = w1 + (size_t)e * DIM_H * (2*DIM_I);
        #pragma unroll
        for (int i = 0; i < 4; i++)
            tile[ty + 8*i][tx] = src[(size_t)(h0 + ty + 8*i) * (2*DIM_I) + d0 + tx];
        __syncthreads();
        __half* dst = g_W1t + (size_t)e * (2*DIM_I) * DIM_H;
        #pragma unroll
        for (int i = 0; i < 4; i++){
            int r = permW1(d0 + ty + 8*i);
            dst[(size_t)r * DIM_H + h0 + tx] = __float2half_rn(tile[tx][ty + 8*i]);
        }
    } else if (bid < PREP_W1_BLKS + PREP_W2_BLKS){
        int b2 = bid - PREP_W1_BLKS;
        int e  = b2 >> 12;
        int h0 = (b2 & 63) * 32;
        int i0 = ((b2 >> 6) & 63) * 32;
        const float* src = w2 + (size_t)e * DIM_I * DIM_H;
        #pragma unroll
        for (int i = 0; i < 4; i++)
            tile[ty + 8*i][tx] = src[(size_t)(i0 + ty + 8*i) * DIM_H + h0 + tx];
        __syncthreads();
        __half* dst = g_W2t + (size_t)e * DIM_H * DIM_I;
        int iL = i0 + tx;
        int ipos = (iL & ~15) | (((iL & 3) << 2) | ((iL >> 2) & 3));
        #pragma unroll
        for (int i = 0; i < 4; i++){
            int h = h0 + ty + 8*i;
            int hl = h & 31;
            int hpos = (h & ~31) | ((((hl >> 1) & 3) << 3) | (((hl >> 3) & 3) << 1) | (hl & 1));
            dst[(size_t)hpos * DIM_I + ipos] = __float2half_rn(tile[tx][ty + 8*i]);
        }
    } else {
        int b3 = bid - PREP_W1_BLKS - PREP_W2_BLKS;
        size_t n4 = (size_t)NUM_E * TOK * DIM_H / 4;
        for (size_t o4 = (size_t)b3 * 256 + tid; o4 < n4;
             o4 += (size_t)PREP_GX_BLKS * 256){
            uint32_t h4 = (uint32_t)(o4 & 511u);
            uint32_t th = (uint32_t)(o4 >> 9);
            uint32_t t  = th & (TOK - 1);
            uint32_t e  = th >> 12;
            uint32_t b  = t >> 9, g = t & (GRP - 1);
            size_t src4 = ((size_t)(b*2048u + g*4u + e) << 9) + h4;
            float4 v = reinterpret_cast<const float4*>(x)[src4];
            __half2 h01 = __floats2half2_rn(v.x, v.y);
            __half2 h23 = __floats2half2_rn(v.z, v.w);
            uint2 pk;
            pk.x = *reinterpret_cast<uint32_t*>(&h01);
            pk.y = *reinterpret_cast<uint32_t*>(&h23);
            reinterpret_cast<uint2*>(g_A1)[o4] = pk;
        }
    }
}

// ---------------- pipelined fp16 mma.sync GEMM (mbarrier pipeline, R14 exact) ----------------
// CTA 128x128, 8 warps (2x4) of 64x32, KC=64 halves (128B rows), 3 stages, 2 CTA/SM.
#define STAGE_B   32768
#define A_BYTES   16384
#define GEMM_SMEM (3 * STAGE_B + 64)

template<int FUSE>
__global__ void __launch_bounds__(256, 2) k_gemm(float* __restrict__ out_){
    constexpr int K = 2048, KIT = 32;   // KC = 64 halves per iter
    constexpr int NTOT = (FUSE == 0) ? 4096 : 2048;

    const __half* Ag = (FUSE == 0) ? g_A1  : g_inter;
    const __half* Bg = (FUSE == 0) ? g_W1t : g_W2t;

    extern __shared__ char smem[];
    const uint32_t sb = smem_u32(smem);
    const uint32_t full_b  = sb + 3 * STAGE_B;
    const uint32_t empty_b = full_b + 24;

    const int tid = threadIdx.x;
    const int wid = tid >> 5, ln = tid & 31;
    const int wm = wid & 1, wn = wid >> 1;      // 2 x 4 warp grid
    const int gid = ln >> 2, tig = ln & 3;

    const int e = blockIdx.z, mt_cta = blockIdx.y, nt_cta = blockIdx.x;
    const __half* Ae = Ag + (size_t)e * TOK  * K + (size_t)mt_cta * 128 * K;
    const __half* Be = Bg + (size_t)e * NTOT * K + (size_t)nt_cta * 128 * K;

    const uint32_t xk   = (uint32_t)(ln & 7);
    const uint32_t axor = ((uint32_t)(ln >> 4) & 1u) ^ xk;
    const uint32_t bxor = ((uint32_t)(ln >> 3) & 1u) ^ xk;
    const uint32_t aRow = (uint32_t)(wm * 64 + (ln & 15));
    const uint32_t bRow = (uint32_t)(wn * 32 + ((ln >> 4) & 1) * 8 + (ln & 7));

    if (tid == 0){
        #pragma unroll
        for (int s = 0; s < 3; s++){
            MBARRIER_INIT(full_b  + 8*s, 256);
            MBARRIER_INIT(empty_b + 8*s, 256);
        }
    }
    __syncthreads();

    auto load_stage = [&](int kc, int s){
        uint32_t stA = sb + (uint32_t)s * STAGE_B;
        uint32_t stB = stA + A_BYTES;
        const __half* gA = Ae + kc * 64;
        const __half* gB = Be + kc * 64;
        #pragma unroll
        for (int i = 0; i < 4; i++){
            int c = tid + i * 256; int row = c >> 3, ch = c & 7;
            cp16(stA + (uint32_t)row * 128u + (uint32_t)((ch ^ (row & 7)) << 4),
                 gA + (size_t)row * K + ch * 8);
        }
        #pragma unroll
        for (int i = 0; i < 4; i++){
            int c = tid + i * 256; int row = c >> 3, ch = c & 7;
            cp16(stB + (uint32_t)row * 128u + (uint32_t)((ch ^ (row & 7)) << 4),
                 gB + (size_t)row * K + ch * 8);
        }
        asm volatile("cp.async.mbarrier.arrive.noinc.shared.b64 [%0];"
                     :: "r"(full_b + 8*s) : "memory");
    };

    float acc[4][4][4];
    #pragma unroll
    for (int mt = 0; mt < 4; mt++)
        #pragma unroll
        for (int nt = 0; nt < 4; nt++)
            #pragma unroll
            for (int q = 0; q < 4; q++) acc[mt][nt][q] = 0.f;

    load_stage(0, 0);
    load_stage(1, 1);

    int sc = 0, pc = 0;
    int sl = 2, jp = 0;

    for (int k = 0; k < KIT; k++){
        MBARRIER_WAIT_PARITY(full_b + 8*sc, pc);

        uint32_t stA = sb + (uint32_t)sc * STAGE_B;
        uint32_t aBase = stA + aRow * 128u;
        uint32_t bBase = stA + A_BYTES + bRow * 128u;
        #pragma unroll
        for (int kk = 0; kk < 4; kk++){            // 4 x K16
            uint32_t c0 = (uint32_t)(kk << 1);
            uint32_t aoff = ((c0 ^ axor) << 4);
            uint32_t boff = ((c0 ^ bxor) << 4);
            uint32_t af[4][4], bf[4][2];
            #pragma unroll
            for (int mt = 0; mt < 4; mt++)
                ldsm4(af[mt], aBase + (uint32_t)mt * 2048u + aoff);
            #pragma unroll
            for (int j = 0; j < 2; j++){
                uint32_t r4[4];
                ldsm4(r4, bBase + (uint32_t)j * 2048u + boff);
                bf[2*j][0] = r4[0]; bf[2*j][1] = r4[1];
                bf[2*j+1][0] = r4[2]; bf[2*j+1][1] = r4[3];
            }
            #pragma unroll
            for (int mt = 0; mt < 4; mt++)
                #pragma unroll
                for (int nt = 0; nt < 4; nt++)
                    mma_f16(acc[mt][nt], af[mt], bf[nt]);
        }

        MBARRIER_ARRIVE(empty_b + 8*sc);
        if (++sc == 3){ sc = 0; pc ^= 1; }

        int kl = k + 2;
        if (kl < KIT){
            if (jp >= 1) MBARRIER_WAIT_PARITY(empty_b + 8*sl, (jp - 1) & 1);
            load_stage(kl, sl);
            if (++sl == 3){ sl = 0; jp++; }
        }
    }

    // ---------------- epilogue ----------------
    if (FUSE == 0){
        __half* ip = g_inter + (size_t)e * TOK * DIM_I;
        int p0 = nt_cta * 64 + wn * 16 + tig * 4;
        #pragma unroll
        for (int mt = 0; mt < 4; mt++){
            int rA = mt_cta * 128 + wm * 64 + mt * 16 + gid;
            __half h0[4], h1[4];
            #pragma unroll
            for (int nt = 0; nt < 4; nt++){
                float g0 = acc[mt][nt][0], u0 = acc[mt][nt][1];
                float g1 = acc[mt][nt][2], u1 = acc[mt][nt][3];
                h0[nt] = __float2half_rn(u0 * (g0 / (1.f + __expf(-g0))));
                h1[nt] = __float2half_rn(u1 * (g1 / (1.f + __expf(-g1))));
            }
            __half2 a0 = __halves2half2(h0[0], h0[1]);
            __half2 a1 = __halves2half2(h0[2], h0[3]);
            __half2 b0 = __halves2half2(h1[0], h1[1]);
            __half2 b1 = __halves2half2(h1[2], h1[3]);
            uint2 u;
            u.x = *reinterpret_cast<uint32_t*>(&a0);
            u.y = *reinterpret_cast<uint32_t*>(&a1);
            *reinterpret_cast<uint2*>(ip + (size_t)rA * DIM_I + p0) = u;
            u.x = *reinterpret_cast<uint32_t*>(&b0);
            u.y = *reinterpret_cast<uint32_t*>(&b1);
            *reinterpret_cast<uint2*>(ip + (size_t)(rA + 8) * DIM_I + p0) = u;
        }
    } else {
        #pragma unroll
        for (int mt = 0; mt < 4; mt++){
            int rA = mt_cta * 128 + wm * 64 + mt * 16 + gid;
            int b0 = rA >> 9, g0 = rA & (GRP - 1);
            int b1 = (rA + 8) >> 9, g1 = (rA + 8) & (GRP - 1);
            size_t o0 = ((size_t)(b0 * 2048 + g0 * 4 + e)) << 11;
            size_t o1 = ((size_t)(b1 * 2048 + g1 * 4 + e)) << 11;
            int hb = nt_cta * 128 + wn * 32 + tig * 8;
            *reinterpret_cast<float4*>(out_ + o0 + hb) =
                make_float4(acc[mt][0][0], acc[mt][0][1], acc[mt][1][0], acc[mt][1][1]);
            *reinterpret_cast<float4*>(out_ + o0 + hb + 4) =
                make_float4(acc[mt][2][0], acc[mt][2][1], acc[mt][3][0], acc[mt][3][1]);
            *reinterpret_cast<float4*>(out_ + o1 + hb) =
                make_float4(acc[mt][0][2], acc[mt][0][3], acc[mt][1][2], acc[mt][1][3]);
            *reinterpret_cast<float4*>(out_ + o1 + hb + 4) =
                make_float4(acc[mt][2][2], acc[mt][2][3], acc[mt][3][2], acc[mt][3][3]);
        }
    }
}

extern "C" void kernel_launch(void* const* d_in, const int* in_sizes, int n_in,
                              void* d_out, int out_size) {
    const float* x  = (const float*)d_in[0];
    const float* w1 = (const float*)d_in[1];
    const float* w2 = (const float*)d_in[2];
    float* out = (float*)d_out;

    cudaFuncSetAttribute(k_gemm<0>, cudaFuncAttributeMaxDynamicSharedMemorySize, GEMM_SMEM);
    cudaFuncSetAttribute(k_gemm<1>, cudaFuncAttributeMaxDynamicSharedMemorySize, GEMM_SMEM);

    k_prep<<<PREP_BLKS, 256>>>(x, w1, w2);
    k_gemm<0><<<dim3(32, 32, 4), 256, GEMM_SMEM>>>(nullptr);
    k_gemm<1><<<dim3(16, 32, 4), 256, GEMM_SMEM>>>(out);
}